// round 10
// baseline (speedup 1.0000x reference)
#include <cuda_runtime.h>
#include <cuda_fp16.h>
#include <cstdint>

#define HH    256
#define MT    128
#define NTH   256
#define STG4  24576          // ring stage: A 8KB(fp16) + W 16KB(fp16)
#define WOFS  8192
#define ALOFF 98304          // aligned tile fp16: 128 x 512B = 64KB
#define CTL   163840
#define SMEM_SZ 164864

__device__ __half g_ce[33554432];      // ce fp16 [131072][256]
__device__ __half g_dh[4194304];       // dh fp16 [16384][256]
__device__ __half g_WT[2][256][512];   // W transposed [n][k] fp16

__device__ __forceinline__ uint32_t h2u(__half2 h) {
    return *reinterpret_cast<uint32_t*>(&h);
}
__device__ __forceinline__ uint32_t s2u(const void* p) {
    uint32_t a;
    asm("{ .reg .u64 t; cvta.to.shared.u64 t, %1; cvt.u32.u64 %0, t; }" : "=r"(a) : "l"(p));
    return a;
}
__device__ __forceinline__ void cpa16(uint32_t dst, const void* src) {
    asm volatile("cp.async.cg.shared.global [%0], [%1], 16;" :: "r"(dst), "l"(src));
}
__device__ __forceinline__ void ldsm4(uint32_t* r, uint32_t addr) {
    asm volatile("ldmatrix.sync.aligned.m8n8.x4.shared.b16 {%0,%1,%2,%3}, [%4];"
        : "=r"(r[0]), "=r"(r[1]), "=r"(r[2]), "=r"(r[3]) : "r"(addr));
}
__device__ __forceinline__ void mma16(float* d, const uint32_t* a, uint32_t b0, uint32_t b1) {
    asm volatile(
        "mma.sync.aligned.m16n8k16.row.col.f32.f16.f16.f32 "
        "{%0,%1,%2,%3}, {%4,%5,%6,%7}, {%8,%9}, {%0,%1,%2,%3};"
        : "+f"(d[0]), "+f"(d[1]), "+f"(d[2]), "+f"(d[3])
        : "r"(a[0]), "r"(a[1]), "r"(a[2]), "r"(a[3]), "r"(b0), "r"(b1));
}
__device__ __forceinline__ void sts32(uint32_t addr, uint32_t v) {
    asm volatile("st.shared.b32 [%0], %1;" :: "r"(addr), "r"(v));
}
__device__ __forceinline__ void sts64(uint32_t addr, uint32_t v0, uint32_t v1) {
    asm volatile("st.shared.v2.b32 [%0], {%1,%2};" :: "r"(addr), "r"(v0), "r"(v1));
}

// ---- prep: fp32 -> fp16 streaming converts ----
__global__ void prep_f16(const float* __restrict__ src, __half* __restrict__ dst) {
    int i = blockIdx.x * blockDim.x + threadIdx.x;   // 8 floats per thread
    const float4* s4 = (const float4*)src;
    float4 v0 = s4[2 * i], v1 = s4[2 * i + 1];
    uint4 o;
    o.x = h2u(__floats2half2_rn(v0.x, v0.y));
    o.y = h2u(__floats2half2_rn(v0.z, v0.w));
    o.z = h2u(__floats2half2_rn(v1.x, v1.y));
    o.w = h2u(__floats2half2_rn(v1.z, v1.w));
    ((uint4*)dst)[i] = o;
}

// ---- prep: W[512][256] -> g_WT[w][256][512] fp16 ----
__global__ void prep_wt(const float* __restrict__ W1, const float* __restrict__ W2) {
    __shared__ float t[32][33];
    int b  = blockIdx.x;            // 2 w x 16 kt x 8 nt
    int w  = b & 1;
    int kt = (b >> 1) & 15;
    int nt = b >> 5;
    const float* W = w ? W2 : W1;
    int tx = threadIdx.x & 31, ty = threadIdx.x >> 5;
    #pragma unroll
    for (int p = 0; p < 4; p++) {
        int k = kt * 32 + ty + p * 8, n = nt * 32 + tx;
        t[ty + p * 8][tx] = W[k * 256 + n];
    }
    __syncthreads();
    #pragma unroll
    for (int p = 0; p < 4; p++) {
        int n = nt * 32 + ty + p * 8, k = kt * 32 + tx;
        g_WT[w][n][k] = __float2half_rn(t[tx][ty + p * 8]);
    }
}

// ---- stage s (0..31): A chunk [128r x 32k fp16] + W chunk [256n x 32k fp16] ----
// phases: 0=char/W1[0:256) 1=gather/W1[256:512) 2=char/W2[0:256) 3=aligned/W2[256:512)
__device__ __forceinline__ void stage(char* smem, uint32_t sb, int row0, int tid,
                                      const int* sidx, int s)
{
    if (s < 32) {
        const int p0 = s >> 3;
        const int kq = (s & 7) * 32;                 // halves
        const uint32_t base = sb + (uint32_t)(s & 3) * STG4;
        // W chunk: 1024 x 16B, 4 per thread (n = tid, c = 0..3)
        {
            const int w  = (p0 >= 2);
            const int wk = kq + ((p0 & 1) ? 256 : 0);
            const int n  = tid;
            const int fn = (n >> 1) & 3;
            const uint32_t drow = base + WOFS + n * 64;
            #pragma unroll
            for (int c = 0; c < 4; c++)
                cpa16(drow + ((c ^ fn) << 4), &g_WT[w][n][wk + c * 8]);
        }
        // A chunk: 512 x 16B, 2 per thread (phases 0-2)
        if (p0 < 3) {
            #pragma unroll
            for (int j = 0; j < 2; j++) {
                int idx = tid * 2 + j;
                int r = idx >> 2, c = idx & 3;
                uint32_t off = r * 64 + ((c ^ ((r >> 1) & 3)) << 4);
                if (p0 == 1) {
                    int so = sidx[r];
                    if (so >= 0) cpa16(base + off, g_dh + (size_t)so * HH + kq + c * 8);
                    else *(float4*)(smem + (size_t)(s & 3) * STG4 + off)
                            = make_float4(0.f, 0.f, 0.f, 0.f);
                } else {
                    cpa16(base + off, g_ce + (size_t)(row0 + r) * HH + kq + c * 8);
                }
            }
        }
    }
    asm volatile("cp.async.commit_group;" ::: "memory");
}

__global__ __launch_bounds__(NTH, 1)
void syl_k(const float* __restrict__ ce, const void* __restrict__ ta,
           const float* __restrict__ b1v, const float* __restrict__ b2v,
           const float* __restrict__ gam, const float* __restrict__ bet,
           float* __restrict__ out)
{
    extern __shared__ char smem[];
    const uint32_t sb = s2u(smem);
    const int tid = threadIdx.x, lane = tid & 31, wid = tid >> 5;
    const int wm = wid >> 2, wn = wid & 3;           // 2m x 4n warp grid, m64n64
    const int g = lane >> 2, tg = lane & 3;
    const int row0 = blockIdx.x * MT;
    int* sidx = (int*)(smem + CTL);
    int* sis  = (int*)(smem + CTL + 512);

    // dtype sniff (int32 vs int64 token_alignment)
    if (wid == 0) {
        const int2* p = (const int2*)ta;
        int2 v = p[lane];
        int ok = (v.y == 0 && v.x >= 0) || (v.y == -1 && v.x < 0);
        ok = __all_sync(0xffffffffu, ok);
        if (lane == 0) *sis = ok;
    }
    __syncthreads();
    if (tid < MT) {
        int gr = row0 + tid;
        long long idx = (*sis) ? ((const long long*)ta)[gr]
                               : (long long)((const int*)ta)[gr];
        int so = -1;
        if (idx >= 0) { int ii = (int)idx; if (ii > 2047) ii = 2047; so = (gr >> 14) * 2048 + ii; }
        sidx[tid] = so;
    }
    __syncthreads();

    // LDSM geometry (validated mapping)
    const int t7   = lane & 7;
    const int rowA = ((lane & 8) ? 8 : 0) + t7;
    const int hiA  = (lane & 16) ? 1 : 0;
    const int rowB = ((lane & 16) ? 8 : 0) + t7;
    const int hiB  = (lane & 8) ? 1 : 0;
    const int f4   = (lane >> 1) & 3;                // swizzle fn for 64B rows
    uint32_t aStg[4], aAl[4], bOff[4];
    #pragma unroll
    for (int mi = 0; mi < 4; mi++) {
        aStg[mi] = (uint32_t)(wm * 64 + mi * 16 + rowA) * 64;
        aAl[mi]  = (uint32_t)(wm * 64 + mi * 16 + rowA) * 512;
    }
    #pragma unroll
    for (int p = 0; p < 4; p++)
        bOff[p] = (uint32_t)(wn * 64 + p * 16 + rowB) * 64;

    float acc[4][8][4];
    #pragma unroll
    for (int mi = 0; mi < 4; mi++)
        #pragma unroll
        for (int ni = 0; ni < 8; ni++)
            #pragma unroll
            for (int c = 0; c < 4; c++) acc[mi][ni][c] = 0.f;

    stage(smem, sb, row0, tid, sidx, 0);
    stage(smem, sb, row0, tid, sidx, 1);
    stage(smem, sb, row0, tid, sidx, 2);

    #pragma unroll 1
    for (int s = 0; s < 32; s++) {
        asm volatile("cp.async.wait_group 2;" ::: "memory");
        __syncthreads();

        stage(smem, sb, row0, tid, sidx, s + 3);

        // ---- compute(s): 2 k16-steps, fragments double-buffered across ksteps ----
        {
            const uint32_t base  = sb + (uint32_t)(s & 3) * STG4;
            const uint32_t wbase = base + WOFS;
            const int p0 = s >> 3;
            uint32_t a[2][4][4], b[2][4][4];

            // load both ksteps' fragments up front (independent -> deep ILP)
            #pragma unroll
            for (int ks = 0; ks < 2; ks++) {
                if (p0 < 3) {
                    uint32_t swa = (uint32_t)(((ks * 2 + hiA) ^ f4) << 4);
                    #pragma unroll
                    for (int mi = 0; mi < 4; mi++) ldsm4(a[ks][mi], base + aStg[mi] + swa);
                } else {
                    uint32_t kk  = (uint32_t)((s & 7) * 4 + ks * 2 + hiA);
                    uint32_t swa = (uint32_t)((kk ^ (uint32_t)t7) << 4);
                    #pragma unroll
                    for (int mi = 0; mi < 4; mi++) ldsm4(a[ks][mi], sb + ALOFF + aAl[mi] + swa);
                }
                uint32_t swb = (uint32_t)(((ks * 2 + hiB) ^ f4) << 4);
                #pragma unroll
                for (int p = 0; p < 4; p++) ldsm4(b[ks][p], wbase + bOff[p] + swb);
            }
            #pragma unroll
            for (int ks = 0; ks < 2; ks++)
                #pragma unroll
                for (int mi = 0; mi < 4; mi++)
                    #pragma unroll
                    for (int ni = 0; ni < 8; ni++)
                        mma16(acc[mi][ni], a[ks][mi],
                              b[ks][ni >> 1][(ni & 1) * 2], b[ks][ni >> 1][(ni & 1) * 2 + 1]);
        }

        if (s == 15) {
            // epilogue 1: aligned = fp16(acc + b1) -> ALOFF tile (swizzled 512B rows)
            #pragma unroll
            for (int mi = 0; mi < 4; mi++)
                #pragma unroll
                for (int ni = 0; ni < 8; ni++) {
                    int col = wn * 64 + ni * 8 + tg * 2;
                    float2 bb = *(const float2*)(b1v + col);
                    #pragma unroll
                    for (int cp = 0; cp < 2; cp++) {
                        int row = wm * 64 + mi * 16 + g + 8 * cp;
                        __half2 h = __floats2half2_rn(acc[mi][ni][2 * cp]     + bb.x,
                                                      acc[mi][ni][2 * cp + 1] + bb.y);
                        uint32_t addr = sb + ALOFF + row * 512
                                      + ((((col >> 3) ^ (row & 7)) << 4) | ((col & 7) * 2));
                        sts32(addr, h2u(h));
                    }
                }
            #pragma unroll
            for (int mi = 0; mi < 4; mi++)
                #pragma unroll
                for (int ni = 0; ni < 8; ni++)
                    #pragma unroll
                    for (int c = 0; c < 4; c++) acc[mi][ni][c] = 0.f;
        }
    }
    __syncthreads();   // all LDSM reads of aligned tile done

    // ---- epilogue 2: feats(fp32) = acc + b2 -> smem offset 0, 1KB rows ----
    #pragma unroll
    for (int mi = 0; mi < 4; mi++)
        #pragma unroll
        for (int ni = 0; ni < 8; ni++) {
            int col = wn * 64 + ni * 8 + tg * 2;
            float2 bb = *(const float2*)(b2v + col);
            #pragma unroll
            for (int cp = 0; cp < 2; cp++) {
                int row = wm * 64 + mi * 16 + g + 8 * cp;
                uint32_t addr = sb + row * 1024 + col * 4;
                sts64(addr,
                      __float_as_uint(acc[mi][ni][2 * cp]     + bb.x),
                      __float_as_uint(acc[mi][ni][2 * cp + 1] + bb.y));
            }
        }
    __syncthreads();

    // ---- LayerNorm + exact GELU + residual (warp per row, 16 rows/warp) ----
    float* F = (float*)smem;
    #pragma unroll 1
    for (int rr = 0; rr < 16; rr++) {
        int r = wid * 16 + rr;
        const float* Frow = F + r * 256;
        float x[8];
        float sm = 0.f, q = 0.f;
        #pragma unroll
        for (int j = 0; j < 8; j++) {
            x[j] = Frow[lane + 32 * j];
            sm += x[j]; q += x[j] * x[j];
        }
        #pragma unroll
        for (int o = 16; o; o >>= 1) {
            sm += __shfl_xor_sync(0xffffffffu, sm, o);
            q  += __shfl_xor_sync(0xffffffffu, q, o);
        }
        float mu  = sm * (1.0f / HH);
        float var = q * (1.0f / HH) - mu * mu;
        float rs  = rsqrtf(var + 1e-5f);
        size_t gb = (size_t)(row0 + r) * HH;
        #pragma unroll
        for (int j = 0; j < 8; j++) {
            int cc = lane + 32 * j;
            float v = (x[j] - mu) * rs * __ldg(gam + cc) + __ldg(bet + cc);
            float gel = 0.5f * v * (1.0f + erff(v * 0.70710678118654752440f));
            out[gb + cc] = ce[gb + cc] + gel;
        }
    }
}

extern "C" void kernel_launch(void* const* d_in, const int* in_sizes, int n_in,
                              void* d_out, int out_size)
{
    const float* ce    = (const float*)d_in[0];
    const void*  ta    = d_in[1];
    const float* dh    = (const float*)d_in[2];
    const float* W1    = (const float*)d_in[3];
    const float* b1    = (const float*)d_in[4];
    const float* W2    = (const float*)d_in[5];
    const float* b2    = (const float*)d_in[6];
    const float* gamma = (const float*)d_in[7];
    const float* beta  = (const float*)d_in[8];
    float* out = (float*)d_out;

    int M = in_sizes[0] / HH;     // 131072 rows
    int grid = M / MT;            // 1024 CTAs

    __half *d_ce16, *d_dh16;
    cudaGetSymbolAddress((void**)&d_ce16, g_ce);
    cudaGetSymbolAddress((void**)&d_dh16, g_dh);

    prep_f16<<<(M * HH / 8 + 511) / 512, 512>>>(ce, d_ce16);
    prep_f16<<<(in_sizes[2] / 8 + 511) / 512, 512>>>(dh, d_dh16);
    prep_wt<<<256, 256>>>(W1, W2);

    cudaFuncSetAttribute(syl_k, cudaFuncAttributeMaxDynamicSharedMemorySize, SMEM_SZ);
    syl_k<<<grid, NTH, SMEM_SZ>>>(ce, ta, b1, b2, gamma, beta, out);
}

// round 11
// speedup vs baseline: 1.2677x; 1.2677x over previous
#include <cuda_runtime.h>
#include <cuda_fp16.h>
#include <cstdint>

#define HH    256
#define MT    128
#define NTH   1024
#define STG4  24576          // ring stage: A 8KB(fp16) + W 16KB(fp16)
#define WOFS  8192
#define ALOFF 98304          // aligned tile fp16: 128 x 512B = 64KB
#define CTL   163840
#define SMEM_SZ 164864

__device__ __half g_ce[33554432];      // ce fp16 [131072][256]
__device__ __half g_dh[4194304];       // dh fp16 [16384][256]
__device__ __half g_WT[2][256][512];   // W transposed [n][k] fp16

__device__ __forceinline__ uint32_t h2u(__half2 h) {
    return *reinterpret_cast<uint32_t*>(&h);
}
__device__ __forceinline__ uint32_t s2u(const void* p) {
    uint32_t a;
    asm("{ .reg .u64 t; cvta.to.shared.u64 t, %1; cvt.u32.u64 %0, t; }" : "=r"(a) : "l"(p));
    return a;
}
__device__ __forceinline__ void cpa16(uint32_t dst, const void* src) {
    asm volatile("cp.async.cg.shared.global [%0], [%1], 16;" :: "r"(dst), "l"(src));
}
__device__ __forceinline__ void ldsm4(uint32_t* r, uint32_t addr) {
    asm volatile("ldmatrix.sync.aligned.m8n8.x4.shared.b16 {%0,%1,%2,%3}, [%4];"
        : "=r"(r[0]), "=r"(r[1]), "=r"(r[2]), "=r"(r[3]) : "r"(addr));
}
__device__ __forceinline__ void mma16(float* d, const uint32_t* a, uint32_t b0, uint32_t b1) {
    asm volatile(
        "mma.sync.aligned.m16n8k16.row.col.f32.f16.f16.f32 "
        "{%0,%1,%2,%3}, {%4,%5,%6,%7}, {%8,%9}, {%0,%1,%2,%3};"
        : "+f"(d[0]), "+f"(d[1]), "+f"(d[2]), "+f"(d[3])
        : "r"(a[0]), "r"(a[1]), "r"(a[2]), "r"(a[3]), "r"(b0), "r"(b1));
}
__device__ __forceinline__ void sts32(uint32_t addr, uint32_t v) {
    asm volatile("st.shared.b32 [%0], %1;" :: "r"(addr), "r"(v));
}
__device__ __forceinline__ void sts64(uint32_t addr, uint32_t v0, uint32_t v1) {
    asm volatile("st.shared.v2.b32 [%0], {%1,%2};" :: "r"(addr), "r"(v0), "r"(v1));
}

// ---- prep: fp32 -> fp16 streaming converts ----
__global__ void prep_f16(const float* __restrict__ src, __half* __restrict__ dst) {
    int i = blockIdx.x * blockDim.x + threadIdx.x;   // 8 floats per thread
    const float4* s4 = (const float4*)src;
    float4 v0 = s4[2 * i], v1 = s4[2 * i + 1];
    uint4 o;
    o.x = h2u(__floats2half2_rn(v0.x, v0.y));
    o.y = h2u(__floats2half2_rn(v0.z, v0.w));
    o.z = h2u(__floats2half2_rn(v1.x, v1.y));
    o.w = h2u(__floats2half2_rn(v1.z, v1.w));
    ((uint4*)dst)[i] = o;
}

// ---- prep: W[512][256] -> g_WT[w][256][512] fp16 ----
__global__ void prep_wt(const float* __restrict__ W1, const float* __restrict__ W2) {
    __shared__ float t[32][33];
    int b  = blockIdx.x;            // 2 w x 16 kt x 8 nt
    int w  = b & 1;
    int kt = (b >> 1) & 15;
    int nt = b >> 5;
    const float* W = w ? W2 : W1;
    int tx = threadIdx.x & 31, ty = threadIdx.x >> 5;
    #pragma unroll
    for (int p = 0; p < 4; p++) {
        int k = kt * 32 + ty + p * 8, n = nt * 32 + tx;
        t[ty + p * 8][tx] = W[k * 256 + n];
    }
    __syncthreads();
    #pragma unroll
    for (int p = 0; p < 4; p++) {
        int n = nt * 32 + ty + p * 8, k = kt * 32 + tx;
        g_WT[w][n][k] = __float2half_rn(t[tx][ty + p * 8]);
    }
}

// ---- stage s (0..31): A chunk [128r x 32k fp16] + W chunk [256n x 32k fp16] ----
// phases: 0=char/W1[0:256) 1=gather/W1[256:512) 2=char/W2[0:256) 3=aligned/W2[256:512)
__device__ __forceinline__ void stage(char* smem, uint32_t sb, int row0, int tid,
                                      const int* sidx, int s)
{
    if (s < 32) {
        const int p0 = s >> 3;
        const int kq = (s & 7) * 32;                 // halves
        const uint32_t base = sb + (uint32_t)(s & 3) * STG4;
        // W chunk: 1024 x 16B, exactly 1 per thread
        {
            const int w  = (p0 >= 2);
            const int wk = kq + ((p0 & 1) ? 256 : 0);
            const int n  = tid >> 2, c = tid & 3;
            const int fn = (n >> 1) & 3;
            cpa16(base + WOFS + n * 64 + ((c ^ fn) << 4), &g_WT[w][n][wk + c * 8]);
        }
        // A chunk: 512 x 16B, threads [0,512) (phases 0-2)
        if (p0 < 3 && tid < 512) {
            const int r = tid >> 2, c = tid & 3;
            const uint32_t off = r * 64 + ((c ^ ((r >> 1) & 3)) << 4);
            if (p0 == 1) {
                int so = sidx[r];
                if (so >= 0) cpa16(base + off, g_dh + (size_t)so * HH + kq + c * 8);
                else *(float4*)(smem + (size_t)(s & 3) * STG4 + off)
                        = make_float4(0.f, 0.f, 0.f, 0.f);
            } else {
                cpa16(base + off, g_ce + (size_t)(row0 + r) * HH + kq + c * 8);
            }
        }
    }
    asm volatile("cp.async.commit_group;" ::: "memory");
}

__global__ __launch_bounds__(NTH, 1)
void syl_k(const float* __restrict__ ce, const void* __restrict__ ta,
           const float* __restrict__ b1v, const float* __restrict__ b2v,
           const float* __restrict__ gam, const float* __restrict__ bet,
           float* __restrict__ out)
{
    extern __shared__ char smem[];
    const uint32_t sb = s2u(smem);
    const int tid = threadIdx.x, lane = tid & 31, wid = tid >> 5;
    const int wm = wid >> 2, wn = wid & 3;           // 8m x 4n warp grid, m16n64
    const int g = lane >> 2, tg = lane & 3;
    const int row0 = blockIdx.x * MT;
    int* sidx = (int*)(smem + CTL);
    int* sis  = (int*)(smem + CTL + 512);

    // dtype sniff (int32 vs int64 token_alignment)
    if (wid == 0) {
        const int2* p = (const int2*)ta;
        int2 v = p[lane];
        int ok = (v.y == 0 && v.x >= 0) || (v.y == -1 && v.x < 0);
        ok = __all_sync(0xffffffffu, ok);
        if (lane == 0) *sis = ok;
    }
    __syncthreads();
    if (tid < MT) {
        int gr = row0 + tid;
        long long idx = (*sis) ? ((const long long*)ta)[gr]
                               : (long long)((const int*)ta)[gr];
        int so = -1;
        if (idx >= 0) { int ii = (int)idx; if (ii > 2047) ii = 2047; so = (gr >> 14) * 2048 + ii; }
        sidx[tid] = so;
    }
    __syncthreads();

    // LDSM geometry (validated mapping)
    const int t7   = lane & 7;
    const int rowA = ((lane & 8) ? 8 : 0) + t7;
    const int hiA  = (lane & 16) ? 1 : 0;
    const int rowB = ((lane & 16) ? 8 : 0) + t7;
    const int hiB  = (lane & 8) ? 1 : 0;
    const int f4   = (lane >> 1) & 3;                // swizzle fn for 64B rows
    const uint32_t aStg = (uint32_t)(wm * 16 + rowA) * 64;
    const uint32_t aAl  = (uint32_t)(wm * 16 + rowA) * 512;
    uint32_t bOff[4];
    #pragma unroll
    for (int p = 0; p < 4; p++)
        bOff[p] = (uint32_t)(wn * 64 + p * 16 + rowB) * 64;

    float acc[8][4];
    #pragma unroll
    for (int ni = 0; ni < 8; ni++)
        #pragma unroll
        for (int c = 0; c < 4; c++) acc[ni][c] = 0.f;

    stage(smem, sb, row0, tid, sidx, 0);
    stage(smem, sb, row0, tid, sidx, 1);
    stage(smem, sb, row0, tid, sidx, 2);

    #pragma unroll 1
    for (int s = 0; s < 32; s++) {
        asm volatile("cp.async.wait_group 2;" ::: "memory");
        __syncthreads();

        stage(smem, sb, row0, tid, sidx, s + 3);

        // ---- compute(s): 2 k16-steps of m16n64 per warp ----
        {
            const uint32_t base  = sb + (uint32_t)(s & 3) * STG4;
            const uint32_t wbase = base + WOFS;
            const int p0 = s >> 3;
            #pragma unroll
            for (int ks = 0; ks < 2; ks++) {
                uint32_t a[4], b[4][4];
                if (p0 < 3) {
                    uint32_t swa = (uint32_t)(((ks * 2 + hiA) ^ f4) << 4);
                    ldsm4(a, base + aStg + swa);
                } else {
                    uint32_t kk  = (uint32_t)((s & 7) * 4 + ks * 2 + hiA);
                    uint32_t swa = (uint32_t)((kk ^ (uint32_t)t7) << 4);
                    ldsm4(a, sb + ALOFF + aAl + swa);
                }
                uint32_t swb = (uint32_t)(((ks * 2 + hiB) ^ f4) << 4);
                #pragma unroll
                for (int p = 0; p < 4; p++) ldsm4(b[p], wbase + bOff[p] + swb);
                #pragma unroll
                for (int ni = 0; ni < 8; ni++)
                    mma16(acc[ni], a,
                          b[ni >> 1][(ni & 1) * 2], b[ni >> 1][(ni & 1) * 2 + 1]);
            }
        }

        if (s == 15) {
            // epilogue 1: aligned = fp16(acc + b1) -> ALOFF tile (swizzled 512B rows)
            #pragma unroll
            for (int ni = 0; ni < 8; ni++) {
                int col = wn * 64 + ni * 8 + tg * 2;
                float2 bb = *(const float2*)(b1v + col);
                #pragma unroll
                for (int cp = 0; cp < 2; cp++) {
                    int row = wm * 16 + g + 8 * cp;
                    __half2 h = __floats2half2_rn(acc[ni][2 * cp]     + bb.x,
                                                  acc[ni][2 * cp + 1] + bb.y);
                    uint32_t addr = sb + ALOFF + row * 512
                                  + ((((col >> 3) ^ (row & 7)) << 4) | ((col & 7) * 2));
                    sts32(addr, h2u(h));
                }
            }
            #pragma unroll
            for (int ni = 0; ni < 8; ni++)
                #pragma unroll
                for (int c = 0; c < 4; c++) acc[ni][c] = 0.f;
        }
    }
    __syncthreads();   // all LDSM reads of aligned tile done

    // ---- epilogue 2: feats(fp32) = acc + b2 -> smem offset 0, 1KB rows ----
    #pragma unroll
    for (int ni = 0; ni < 8; ni++) {
        int col = wn * 64 + ni * 8 + tg * 2;
        float2 bb = *(const float2*)(b2v + col);
        #pragma unroll
        for (int cp = 0; cp < 2; cp++) {
            int row = wm * 16 + g + 8 * cp;
            uint32_t addr = sb + row * 1024 + col * 4;
            sts64(addr,
                  __float_as_uint(acc[ni][2 * cp]     + bb.x),
                  __float_as_uint(acc[ni][2 * cp + 1] + bb.y));
        }
    }
    __syncthreads();

    // ---- LayerNorm + exact GELU + residual (warp per row, 4 rows/warp) ----
    float* F = (float*)smem;
    #pragma unroll 1
    for (int rr = 0; rr < 4; rr++) {
        int r = wid * 4 + rr;
        const float* Frow = F + r * 256;
        float x[8];
        float sm = 0.f, q = 0.f;
        #pragma unroll
        for (int j = 0; j < 8; j++) {
            x[j] = Frow[lane + 32 * j];
            sm += x[j]; q += x[j] * x[j];
        }
        #pragma unroll
        for (int o = 16; o; o >>= 1) {
            sm += __shfl_xor_sync(0xffffffffu, sm, o);
            q  += __shfl_xor_sync(0xffffffffu, q, o);
        }
        float mu  = sm * (1.0f / HH);
        float var = q * (1.0f / HH) - mu * mu;
        float rs  = rsqrtf(var + 1e-5f);
        size_t gb = (size_t)(row0 + r) * HH;
        #pragma unroll
        for (int j = 0; j < 8; j++) {
            int cc = lane + 32 * j;
            float v = (x[j] - mu) * rs * __ldg(gam + cc) + __ldg(bet + cc);
            float gel = 0.5f * v * (1.0f + erff(v * 0.70710678118654752440f));
            out[gb + cc] = ce[gb + cc] + gel;
        }
    }
}

extern "C" void kernel_launch(void* const* d_in, const int* in_sizes, int n_in,
                              void* d_out, int out_size)
{
    const float* ce    = (const float*)d_in[0];
    const void*  ta    = d_in[1];
    const float* dh    = (const float*)d_in[2];
    const float* W1    = (const float*)d_in[3];
    const float* b1    = (const float*)d_in[4];
    const float* W2    = (const float*)d_in[5];
    const float* b2    = (const float*)d_in[6];
    const float* gamma = (const float*)d_in[7];
    const float* beta  = (const float*)d_in[8];
    float* out = (float*)d_out;

    int M = in_sizes[0] / HH;     // 131072 rows
    int grid = M / MT;            // 1024 CTAs

    __half *d_ce16, *d_dh16;
    cudaGetSymbolAddress((void**)&d_ce16, g_ce);
    cudaGetSymbolAddress((void**)&d_dh16, g_dh);

    prep_f16<<<(M * HH / 8 + 511) / 512, 512>>>(ce, d_ce16);
    prep_f16<<<(in_sizes[2] / 8 + 511) / 512, 512>>>(dh, d_dh16);
    prep_wt<<<256, 256>>>(W1, W2);

    cudaFuncSetAttribute(syl_k, cudaFuncAttributeMaxDynamicSharedMemorySize, SMEM_SZ);
    syl_k<<<grid, NTH, SMEM_SZ>>>(ce, ta, b1, b2, gamma, beta, out);
}